// round 3
// baseline (speedup 1.0000x reference)
#include <cuda_runtime.h>

// Problem constants
#define NB 16
#define CI 32
#define CO 32
#define HH 224
#define WW 224
#define TILE_H 8
#define TILE_W 32
#define GX 7     // 224 / TILE_W
#define GY 28    // 224 / TILE_H
#define NBLK (GX*GY*NB)   // 3136 conv blocks

// Scratch (no allocations allowed -> __device__ globals)
__device__ double g_part[NBLK * 64];     // per-block per-channel [sum(0..31), sumsq(32..63)]
__device__ float  g_scale[CO];
__device__ float  g_bias[CO];

// ---------------------------------------------------------------------------
// Packed f32x2 helpers (sm_103a FFMA2 — only reachable via PTX fma.rn.f32x2)
// ---------------------------------------------------------------------------
__device__ __forceinline__ unsigned long long pack2(float w) {
    unsigned long long r;
    asm("mov.b64 %0, {%1, %1};" : "=l"(r) : "f"(w));
    return r;
}
__device__ __forceinline__ void ffma2(unsigned long long& d,
                                      unsigned long long a,
                                      unsigned long long b) {
    asm("fma.rn.f32x2 %0, %1, %2, %3;" : "=l"(d) : "l"(a), "l"(b), "l"(d));
}
__device__ __forceinline__ float lo32(unsigned long long v) {
    return __uint_as_float((unsigned)v);
}
__device__ __forceinline__ float hi32(unsigned long long v) {
    return __uint_as_float((unsigned)(v >> 32));
}

// Shared layout (floats):
//   ws : [c*9+k][o]  -> 32ch*9tap*32oc = 9216
//   xsA: 16c x 10rows x 36cols (col j = x[w0+j-1], halo-aligned)   = 5760
//   xsS: 16c x 10rows x 32cols (col j = x[w0+j]  , shifted copy)   = 5120
#define WS_FLOATS   (CI * 9 * 32)
#define XSA_FLOATS  (16 * 10 * 36)
#define XSS_FLOATS  (16 * 10 * 32)
#define SMEM_FLOATS (WS_FLOATS + XSA_FLOATS + XSS_FLOATS)

// ---------------------------------------------------------------------------
// Conv: binarized-weight 3x3, pad 1, everything in packed f32x2 FFMA2.
// One block = (n, 8h x 32w) tile, all 32 output channels.
// Warp = 32 output channels at same h -> all x LDS are broadcasts.
// Channels staged in two halves of 16 to keep smem at 2 CTAs/SM.
// ---------------------------------------------------------------------------
__global__ __launch_bounds__(256, 2)
void conv_kernel(const float* __restrict__ x, const float* __restrict__ wgt,
                 float* __restrict__ out)
{
    extern __shared__ float smem[];
    float* ws  = smem;                          // 9216
    float* xsA = smem + WS_FLOATS;              // 5760
    float* xsS = smem + WS_FLOATS + XSA_FLOATS; // 5120
    __shared__ double sred[512];

    const int tid = threadIdx.x;
    const int o   = tid & 31;         // output channel
    const int hg  = tid >> 5;         // row within tile (0..7)
    const int w0  = blockIdx.x * TILE_W;
    const int h0  = blockIdx.y * TILE_H;
    const int n   = blockIdx.z;

    // Binarize weights into shared: ws[(c*9+k)*32 + o] = sign(wgt[o][c][k])
    for (int i = tid; i < WS_FLOATS; i += 256) {
        int oo = i & 31;
        int j  = i >> 5;               // c*9+k
        ws[i] = (wgt[oo * 288 + j] >= 0.0f) ? 1.0f : -1.0f;
    }

    unsigned long long acc[16];        // 32 outputs as 16 f32x2 pairs
#pragma unroll
    for (int i = 0; i < 16; i++) acc[i] = 0ull;

    for (int half = 0; half < 2; half++) {
        // ---- stage 16 channels into xsA (halo-aligned) and xsS (shift-1) ----
        __syncthreads();   // protect previous iteration's reads
        for (int i = tid; i < XSA_FLOATS; i += 256) {
            int c   = i / 360;
            int rem = i - c * 360;
            int rr  = rem / 36;
            int cc  = rem - rr * 36;
            int gh = h0 + rr - 1;
            int gw = w0 + cc - 1;
            float v = 0.0f;
            if (gh >= 0 && gh < HH && gw >= 0 && gw < WW)
                v = x[((n * CI + (half * 16 + c)) * HH + gh) * WW + gw];
            xsA[i] = v;
        }
        for (int i = tid; i < XSS_FLOATS; i += 256) {
            int c   = i >> 9;              // /320? no: 10*32=320 per channel
            c = i / 320;
            int rem = i - c * 320;
            int rr  = rem >> 5;
            int cc  = rem & 31;
            int gh = h0 + rr - 1;
            float v = 0.0f;
            if (gh >= 0 && gh < HH)
                v = x[((n * CI + (half * 16 + c)) * HH + gh) * WW + (w0 + cc)];
            xsS[i] = v;
        }
        __syncthreads();

#pragma unroll 1
        for (int cg = 0; cg < 16; cg++) {
            const int c = half * 16 + cg;
            // 9 packed weights {w,w}
            unsigned long long w2[9];
#pragma unroll
            for (int k = 0; k < 9; k++)
                w2[k] = pack2(ws[(c * 9 + k) * 32 + o]);

#pragma unroll
            for (int dy = 0; dy < 3; dy++) {
                const float* rowA = xsA + cg * 360 + (hg + dy) * 36;
                const float* rowS = xsS + cg * 320 + (hg + dy) * 32;
                const unsigned long long wA = w2[dy * 3 + 0];
                const unsigned long long wB = w2[dy * 3 + 1];
                const unsigned long long wC = w2[dy * 3 + 2];
#pragma unroll
                for (int q = 0; q < 4; q++) {
                    // pairs A[4q..4q+4] from aligned copy, S[4q..4q+3] from shifted
                    const ulonglong2* pa = (const ulonglong2*)(rowA + 8 * q);
                    const ulonglong2* ps = (const ulonglong2*)(rowS + 8 * q);
                    ulonglong2 a01 = pa[0];
                    ulonglong2 a23 = pa[1];
                    unsigned long long a4 = *(const unsigned long long*)(rowA + 8 * q + 8);
                    ulonglong2 s01 = ps[0];
                    ulonglong2 s23 = ps[1];

                    ffma2(acc[4*q+0], a01.x, wA);
                    ffma2(acc[4*q+0], s01.x, wB);
                    ffma2(acc[4*q+0], a01.y, wC);

                    ffma2(acc[4*q+1], a01.y, wA);
                    ffma2(acc[4*q+1], s01.y, wB);
                    ffma2(acc[4*q+1], a23.x, wC);

                    ffma2(acc[4*q+2], a23.x, wA);
                    ffma2(acc[4*q+2], s23.x, wB);
                    ffma2(acc[4*q+2], a23.y, wC);

                    ffma2(acc[4*q+3], a23.y, wA);
                    ffma2(acc[4*q+3], s23.y, wB);
                    ffma2(acc[4*q+3], a4,    wC);
                }
            }
        }
    }

    // Write conv output (contiguous 128B per thread, vectorized) + stats
    const int base = ((n * CO + o) * HH + (h0 + hg)) * WW + w0;
    float4* op = (float4*)&out[base];
    double s = 0.0, ssq = 0.0;
#pragma unroll
    for (int q = 0; q < 8; q++) {
        float4 t;
        t.x = lo32(acc[2*q+0]); t.y = hi32(acc[2*q+0]);
        t.z = lo32(acc[2*q+1]); t.w = hi32(acc[2*q+1]);
        op[q] = t;
        double vx = (double)t.x, vy = (double)t.y, vz = (double)t.z, vw = (double)t.w;
        s   += vx + vy + vz + vw;
        ssq += vx*vx + vy*vy + vz*vz + vw*vw;
    }
    sred[o * 8 + hg]       = s;
    sred[256 + o * 8 + hg] = ssq;
    __syncthreads();

    const int bflat = blockIdx.x + GX * (blockIdx.y + GY * blockIdx.z);
    if (tid < 64) {
        int cch   = tid & 31;
        int which = tid >> 5;           // 0 = sum, 1 = sumsq
        double a = 0.0;
#pragma unroll
        for (int j = 0; j < 8; j++)     // fixed order -> deterministic
            a += sred[which * 256 + cch * 8 + j];
        g_part[bflat * 64 + which * 32 + cch] = a;
    }
}

// ---------------------------------------------------------------------------
// Reduce per-block partials -> per-channel BN scale/bias (deterministic tree)
// ---------------------------------------------------------------------------
__global__ void reduce_kernel(const float* __restrict__ gamma,
                              const float* __restrict__ beta)
{
    const int c = blockIdx.x;     // 32 blocks
    const int t = threadIdx.x;    // 256 threads
    __shared__ double sh[512];

    double s = 0.0, ssq = 0.0;
    for (int b = t; b < NBLK; b += 256) {
        s   += g_part[b * 64 + c];
        ssq += g_part[b * 64 + 32 + c];
    }
    sh[t]       = s;
    sh[256 + t] = ssq;
    __syncthreads();
    for (int step = 128; step > 0; step >>= 1) {
        if (t < step) {
            sh[t]       += sh[t + step];
            sh[256 + t] += sh[256 + t + step];
        }
        __syncthreads();
    }
    if (t == 0) {
        const double Nc   = (double)NB * HH * WW;
        double mean = sh[0] / Nc;
        double var  = sh[256] / Nc - mean * mean;
        double inv  = 1.0 / sqrt(var + 1e-5);
        double sc   = (double)gamma[c] * inv;
        g_scale[c] = (float)sc;
        g_bias[c]  = (float)((double)beta[c] - mean * sc);
    }
}

// ---------------------------------------------------------------------------
// Finalize: BN affine + hardtanh + 2-bit quantize (round-half-even), in place.
// 6,422,528 float4s = exactly 25088 blocks x 256 threads.
// ---------------------------------------------------------------------------
__device__ __forceinline__ float qclamp(float v, float sc, float bi)
{
    float y = fmaf(v, sc, bi);
    y = fminf(fmaxf(y, -1.0f), 1.0f);
    return rintf(y * 2.0f) * 0.5f;
}

__global__ void finalize_kernel(float4* __restrict__ out)
{
    const unsigned i = blockIdx.x * 256u + threadIdx.x;   // < 6422528
    const int c = (int)((i / 12544u) & 31u);              // 12544 float4s per (n,c) plane
    const float sc = g_scale[c];
    const float bi = g_bias[c];
    float4 v = out[i];
    v.x = qclamp(v.x, sc, bi);
    v.y = qclamp(v.y, sc, bi);
    v.z = qclamp(v.z, sc, bi);
    v.w = qclamp(v.w, sc, bi);
    out[i] = v;
}

// ---------------------------------------------------------------------------
extern "C" void kernel_launch(void* const* d_in, const int* in_sizes, int n_in,
                              void* d_out, int out_size)
{
    const float* x     = (const float*)d_in[0];   // (16,32,224,224)
    const float* wgt   = (const float*)d_in[1];   // (32,32,3,3) OIHW
    const float* gamma = (const float*)d_in[2];   // (32,)
    const float* beta  = (const float*)d_in[3];   // (32,)
    float* out = (float*)d_out;                   // (16,32,224,224)

    const size_t shmem = (size_t)SMEM_FLOATS * sizeof(float);  // 80,384 B
    cudaFuncSetAttribute(conv_kernel, cudaFuncAttributeMaxDynamicSharedMemorySize, (int)shmem);

    conv_kernel<<<dim3(GX, GY, NB), 256, shmem>>>(x, wgt, out);
    reduce_kernel<<<32, 256>>>(gamma, beta);
    finalize_kernel<<<25088, 256>>>((float4*)d_out);
}